// round 5
// baseline (speedup 1.0000x reference)
#include <cuda_runtime.h>
#include <cuda_bf16.h>

// y[n] = beta_0 + sum_{i<7,j<64} x[n,i,j] * w[i,j],  w = gamma^T @ alpha (rank 64)
// x: [131072, 7, 64] fp32. HBM-bound: 235 MB read -> ~34us floor.
// Single launch: each block computes w (448 floats) into smem at entry
// (gamma/alpha are L2-resident after wave 1; cost ~hundreds of cycles),
// then R3's mainloop: 2 rows/warp = 224 float4 = exactly 7 full warp loads.
// NOTE: plain LDG (no __ldcs) — evict-first regressed DRAM% in R2/R4.

#define N_GAMMA 7
#define N_ALPHA 64
#define RANK    64
#define W_ELEMS (N_GAMMA * N_ALPHA)   // 448
#define W_F4    (W_ELEMS / 4)         // 112
#define ROWS_PER_WARP 2
#define WARPS_PER_BLOCK 8

__device__ __forceinline__ float fma4(float acc, float4 v, float4 w) {
    acc = fmaf(v.x, w.x, acc);
    acc = fmaf(v.y, w.y, acc);
    acc = fmaf(v.z, w.z, acc);
    acc = fmaf(v.w, w.w, acc);
    return acc;
}

__global__ __launch_bounds__(256) void cp_fused_kernel(
    const float* __restrict__ x,
    const float* __restrict__ beta0_p,
    const float* __restrict__ gamma,   // [64,7]
    const float* __restrict__ alpha,   // [64,64]
    float* __restrict__ y,
    int n_rows)
{
    __shared__ float4 sw[W_F4];

    // --- In-block w computation: thread t (< 112) computes w[4t..4t+3]. ---
    {
        int t = threadIdx.x;
        if (t < W_F4) {
            int i0 = t >> 4;       // gamma column, 0..6
            int jc = t & 15;       // alpha float4 column, 0..15
            const float4* a4 = reinterpret_cast<const float4*>(alpha);
            float4 s = make_float4(0.f, 0.f, 0.f, 0.f);
#pragma unroll
            for (int r = 0; r < RANK; r++) {
                float g = gamma[r * N_GAMMA + i0];
                float4 av = a4[r * (N_ALPHA / 4) + jc];
                s.x = fmaf(g, av.x, s.x);
                s.y = fmaf(g, av.y, s.y);
                s.z = fmaf(g, av.z, s.z);
                s.w = fmaf(g, av.w, s.w);
            }
            sw[t] = s;
        }
    }
    __syncthreads();

    int warp = threadIdx.x >> 5;
    int lane = threadIdx.x & 31;
    int n0 = (blockIdx.x * WARPS_PER_BLOCK + warp) * ROWS_PER_WARP;
    if (n0 >= n_rows) return;

    const float4* xr = reinterpret_cast<const float4*>(x + (size_t)n0 * W_ELEMS);

    // 7 independent full-width 16B loads (224 float4 = 2 rows, perfectly coalesced).
    float4 v0 = xr[lane];
    float4 v1 = xr[lane + 32];
    float4 v2 = xr[lane + 64];
    float4 v3 = xr[lane + 96];
    float4 v4 = xr[lane + 128];
    float4 v5 = xr[lane + 160];
    float4 v6 = xr[lane + 192];

    // w4 index = (lane + 32t) % 112 ; element belongs to row A if (lane+32t) < 112.
    float accA = 0.f, accB = 0.f;
    accA = fma4(accA, v0, sw[lane]);
    accA = fma4(accA, v1, sw[lane + 32]);
    accA = fma4(accA, v2, sw[lane + 64]);
    {   // t=3: lanes 0-15 -> row A (w idx lane+96); lanes 16-31 -> row B (w idx lane-16)
        float4 w3 = sw[(lane < 16) ? (lane + 96) : (lane - 16)];
        float d = fma4(0.f, v3, w3);
        if (lane < 16) accA += d; else accB += d;
    }
    accB = fma4(accB, v4, sw[lane + 16]);
    accB = fma4(accB, v5, sw[lane + 48]);
    accB = fma4(accB, v6, sw[lane + 80]);

    // Two interleaved butterfly reductions.
#pragma unroll
    for (int o = 16; o > 0; o >>= 1) {
        accA += __shfl_xor_sync(0xFFFFFFFFu, accA, o);
        accB += __shfl_xor_sync(0xFFFFFFFFu, accB, o);
    }

    if (lane < ROWS_PER_WARP && n0 + lane < n_rows) {
        float r = (lane == 0) ? accA : accB;
        y[n0 + lane] = beta0_p[0] + r;
    }
}

extern "C" void kernel_launch(void* const* d_in, const int* in_sizes, int n_in,
                              void* d_out, int out_size)
{
    const float* x     = (const float*)d_in[0];
    const float* beta0 = (const float*)d_in[1];
    const float* gamma = (const float*)d_in[2];
    const float* alpha = (const float*)d_in[3];
    float* y = (float*)d_out;

    int n_rows = in_sizes[0] / W_ELEMS;

    int rows_per_block = WARPS_PER_BLOCK * ROWS_PER_WARP;  // 16
    int grid = (n_rows + rows_per_block - 1) / rows_per_block;
    cp_fused_kernel<<<grid, 256>>>(x, beta0, gamma, alpha, y, n_rows);
}

// round 6
// speedup vs baseline: 1.3442x; 1.3442x over previous
#include <cuda_runtime.h>
#include <cuda_bf16.h>
#include <cuda_device_runtime_api.h>

// y[n] = beta_0 + sum_{i<7,j<64} x[n,i,j] * w[i,j],  w = gamma^T @ alpha (rank 64)
// x: [131072, 7, 64] fp32. HBM-bound: 235 MB read -> ~34us floor.
// Two kernels + PDL overlap: prep computes w; main launches programmatically,
// issues its x loads BEFORE griddepcontrol.wait so wave-1 DRAM latency hides
// prep execution. Mainloop identical to R3 (38.9us kernel, DRAM 77.8%).

#define N_GAMMA 7
#define N_ALPHA 64
#define RANK    64
#define W_ELEMS (N_GAMMA * N_ALPHA)   // 448
#define W_F4    (W_ELEMS / 4)         // 112
#define ROWS_PER_WARP 2
#define WARPS_PER_BLOCK 8

__device__ float g_w[W_ELEMS];

// Collapse CP factors into the 7x64 weight matrix. One block, 448 threads.
__global__ void prep_w_kernel(const float* __restrict__ gamma,   // [64,7]
                              const float* __restrict__ alpha)   // [64,64]
{
    int idx = threadIdx.x;
    if (idx >= W_ELEMS) return;
    int i = idx / N_ALPHA;
    int j = idx % N_ALPHA;
    float s = 0.0f;
#pragma unroll
    for (int r = 0; r < RANK; r++)
        s = fmaf(gamma[r * N_GAMMA + i], alpha[r * N_ALPHA + j], s);
    g_w[idx] = s;
    // Implicit programmatic completion trigger at kernel end.
}

__device__ __forceinline__ float fma4(float acc, float4 v, float4 w) {
    acc = fmaf(v.x, w.x, acc);
    acc = fmaf(v.y, w.y, acc);
    acc = fmaf(v.z, w.z, acc);
    acc = fmaf(v.w, w.w, acc);
    return acc;
}

__global__ __launch_bounds__(256) void cp_dot_kernel(
    const float* __restrict__ x,
    const float* __restrict__ beta0_p,
    float* __restrict__ y,
    int n_rows)
{
    __shared__ float4 sw[W_F4];

    int warp = threadIdx.x >> 5;
    int lane = threadIdx.x & 31;
    int n0 = (blockIdx.x * WARPS_PER_BLOCK + warp) * ROWS_PER_WARP;

    // --- Issue x loads FIRST: independent of prep kernel's w. ---
    float4 v0, v1, v2, v3, v4, v5, v6;
    bool active = (n0 < n_rows);
    if (active) {
        const float4* xr = reinterpret_cast<const float4*>(x + (size_t)n0 * W_ELEMS);
        v0 = xr[lane];
        v1 = xr[lane + 32];
        v2 = xr[lane + 64];
        v3 = xr[lane + 96];
        v4 = xr[lane + 128];
        v5 = xr[lane + 160];
        v6 = xr[lane + 192];
    }

    // --- Wait for prep kernel's writes (PDL); then stage w. ---
    cudaGridDependencySynchronize();

    const float4* wg4 = reinterpret_cast<const float4*>(g_w);
    if (threadIdx.x < W_F4)
        sw[threadIdx.x] = wg4[threadIdx.x];
    __syncthreads();

    if (!active) return;

    // w4 index = (lane + 32t) % 112 ; element belongs to row A if (lane+32t) < 112.
    float accA = 0.f, accB = 0.f;
    accA = fma4(accA, v0, sw[lane]);
    accA = fma4(accA, v1, sw[lane + 32]);
    accA = fma4(accA, v2, sw[lane + 64]);
    {   // t=3: lanes 0-15 -> row A (w idx lane+96); lanes 16-31 -> row B (w idx lane-16)
        float4 w3 = sw[(lane < 16) ? (lane + 96) : (lane - 16)];
        float d = fma4(0.f, v3, w3);
        if (lane < 16) accA += d; else accB += d;
    }
    accB = fma4(accB, v4, sw[lane + 16]);
    accB = fma4(accB, v5, sw[lane + 48]);
    accB = fma4(accB, v6, sw[lane + 80]);

    // Two interleaved butterfly reductions.
#pragma unroll
    for (int o = 16; o > 0; o >>= 1) {
        accA += __shfl_xor_sync(0xFFFFFFFFu, accA, o);
        accB += __shfl_xor_sync(0xFFFFFFFFu, accB, o);
    }

    if (lane < ROWS_PER_WARP && n0 + lane < n_rows) {
        float r = (lane == 0) ? accA : accB;
        y[n0 + lane] = beta0_p[0] + r;
    }
}

extern "C" void kernel_launch(void* const* d_in, const int* in_sizes, int n_in,
                              void* d_out, int out_size)
{
    const float* x     = (const float*)d_in[0];
    const float* beta0 = (const float*)d_in[1];
    const float* gamma = (const float*)d_in[2];
    const float* alpha = (const float*)d_in[3];
    float* y = (float*)d_out;

    int n_rows = in_sizes[0] / W_ELEMS;

    prep_w_kernel<<<1, W_ELEMS>>>(gamma, alpha);

    int rows_per_block = WARPS_PER_BLOCK * ROWS_PER_WARP;  // 16
    int grid = (n_rows + rows_per_block - 1) / rows_per_block;

    // Launch main kernel with programmatic stream serialization: it may begin
    // while prep is in flight; griddepcontrol.wait inside provides ordering.
    cudaLaunchConfig_t cfg = {};
    cfg.gridDim  = dim3(grid, 1, 1);
    cfg.blockDim = dim3(256, 1, 1);
    cfg.dynamicSmemBytes = 0;
    cfg.stream = 0;
    cudaLaunchAttribute attrs[1];
    attrs[0].id = cudaLaunchAttributeProgrammaticStreamSerialization;
    attrs[0].val.programmaticStreamSerializationAllowed = 1;
    cfg.attrs = attrs;
    cfg.numAttrs = 1;

    cudaError_t err = cudaLaunchKernelEx(&cfg, cp_dot_kernel, x, beta0, y, n_rows);
    if (err != cudaSuccess) {
        // Fallback: plain serialized launch (still correct).
        cp_dot_kernel<<<grid, 256>>>(x, beta0, y, n_rows);
    }
}

// round 7
// speedup vs baseline: 1.3951x; 1.0378x over previous
#include <cuda_runtime.h>
#include <cuda_bf16.h>
#include <cuda_device_runtime_api.h>

// y[n] = beta_0 + sum_{i<7,j<64} x[n,i,j] * w[i,j],  w = gamma^T @ alpha (rank 64)
// x: [131072, 7, 64] fp32. HBM-bound: 235 MB read -> ~34us kernel floor.
// Two kernels + PDL: prep triggers programmatic launch IMMEDIATELY, so the
// main kernel's wave-1 blocks schedule during prep, issue their x loads
// (independent of w), and only the griddepcontrol.wait orders against prep's
// writes. Mainloop identical to R6 (37.8us kernel, DRAM 80.1%).

#define N_GAMMA 7
#define N_ALPHA 64
#define RANK    64
#define W_ELEMS (N_GAMMA * N_ALPHA)   // 448
#define W_F4    (W_ELEMS / 4)         // 112
#define ROWS_PER_WARP 2
#define WARPS_PER_BLOCK 8

__device__ float g_w[W_ELEMS];

// Collapse CP factors into the 7x64 weight matrix. One block, 448 threads.
// Coalesced smem staging; PDL trigger fired first thing.
__global__ void prep_w_kernel(const float* __restrict__ gamma,   // [64,7]
                              const float* __restrict__ alpha)   // [64,64]
{
    // Let the dependent kernel start scheduling NOW; its griddepcontrol.wait
    // still orders against this kernel's completion.
    cudaTriggerProgrammaticLaunchCompletion();

    __shared__ float s_alpha[RANK * N_ALPHA];   // 16 KB
    __shared__ float s_gamma[RANK * N_GAMMA];   // 1.75 KB

    int t = threadIdx.x;

    // Coalesced float4 staging of alpha (1024 float4).
    const float4* a4 = reinterpret_cast<const float4*>(alpha);
    float4* sa4 = reinterpret_cast<float4*>(s_alpha);
    for (int i = t; i < RANK * N_ALPHA / 4; i += blockDim.x)
        sa4[i] = a4[i];
    if (t < RANK * N_GAMMA)
        s_gamma[t] = gamma[t];
    __syncthreads();

    if (t >= W_ELEMS) return;
    int i = t / N_ALPHA;
    int j = t % N_ALPHA;
    float s = 0.0f;
#pragma unroll
    for (int r = 0; r < RANK; r++)
        s = fmaf(s_gamma[r * N_GAMMA + i], s_alpha[r * N_ALPHA + j], s);
    g_w[t] = s;
}

__device__ __forceinline__ float fma4(float acc, float4 v, float4 w) {
    acc = fmaf(v.x, w.x, acc);
    acc = fmaf(v.y, w.y, acc);
    acc = fmaf(v.z, w.z, acc);
    acc = fmaf(v.w, w.w, acc);
    return acc;
}

__global__ __launch_bounds__(256) void cp_dot_kernel(
    const float* __restrict__ x,
    const float* __restrict__ beta0_p,
    float* __restrict__ y,
    int n_rows)
{
    __shared__ float4 sw[W_F4];

    int warp = threadIdx.x >> 5;
    int lane = threadIdx.x & 31;
    int n0 = (blockIdx.x * WARPS_PER_BLOCK + warp) * ROWS_PER_WARP;

    // --- Issue x loads FIRST: independent of prep kernel's w. ---
    float4 v0, v1, v2, v3, v4, v5, v6;
    bool active = (n0 < n_rows);
    if (active) {
        const float4* xr = reinterpret_cast<const float4*>(x + (size_t)n0 * W_ELEMS);
        v0 = xr[lane];
        v1 = xr[lane + 32];
        v2 = xr[lane + 64];
        v3 = xr[lane + 96];
        v4 = xr[lane + 128];
        v5 = xr[lane + 160];
        v6 = xr[lane + 192];
    }

    // --- Wait for prep kernel's writes (PDL); then stage w. ---
    cudaGridDependencySynchronize();

    const float4* wg4 = reinterpret_cast<const float4*>(g_w);
    if (threadIdx.x < W_F4)
        sw[threadIdx.x] = wg4[threadIdx.x];
    __syncthreads();

    if (!active) return;

    // w4 index = (lane + 32t) % 112 ; element belongs to row A if (lane+32t) < 112.
    float accA = 0.f, accB = 0.f;
    accA = fma4(accA, v0, sw[lane]);
    accA = fma4(accA, v1, sw[lane + 32]);
    accA = fma4(accA, v2, sw[lane + 64]);
    {   // t=3: lanes 0-15 -> row A (w idx lane+96); lanes 16-31 -> row B (w idx lane-16)
        float4 w3 = sw[(lane < 16) ? (lane + 96) : (lane - 16)];
        float d = fma4(0.f, v3, w3);
        if (lane < 16) accA += d; else accB += d;
    }
    accB = fma4(accB, v4, sw[lane + 16]);
    accB = fma4(accB, v5, sw[lane + 48]);
    accB = fma4(accB, v6, sw[lane + 80]);

    // Two interleaved butterfly reductions.
#pragma unroll
    for (int o = 16; o > 0; o >>= 1) {
        accA += __shfl_xor_sync(0xFFFFFFFFu, accA, o);
        accB += __shfl_xor_sync(0xFFFFFFFFu, accB, o);
    }

    if (lane < ROWS_PER_WARP && n0 + lane < n_rows) {
        float r = (lane == 0) ? accA : accB;
        y[n0 + lane] = beta0_p[0] + r;
    }
}

extern "C" void kernel_launch(void* const* d_in, const int* in_sizes, int n_in,
                              void* d_out, int out_size)
{
    const float* x     = (const float*)d_in[0];
    const float* beta0 = (const float*)d_in[1];
    const float* gamma = (const float*)d_in[2];
    const float* alpha = (const float*)d_in[3];
    float* y = (float*)d_out;

    int n_rows = in_sizes[0] / W_ELEMS;

    prep_w_kernel<<<1, 448>>>(gamma, alpha);

    int rows_per_block = WARPS_PER_BLOCK * ROWS_PER_WARP;  // 16
    int grid = (n_rows + rows_per_block - 1) / rows_per_block;

    // Secondary launch with programmatic stream serialization: may begin while
    // prep is in flight; griddepcontrol.wait inside provides ordering.
    cudaLaunchConfig_t cfg = {};
    cfg.gridDim  = dim3(grid, 1, 1);
    cfg.blockDim = dim3(256, 1, 1);
    cfg.dynamicSmemBytes = 0;
    cfg.stream = 0;
    cudaLaunchAttribute attrs[1];
    attrs[0].id = cudaLaunchAttributeProgrammaticStreamSerialization;
    attrs[0].val.programmaticStreamSerializationAllowed = 1;
    cfg.attrs = attrs;
    cfg.numAttrs = 1;

    cudaError_t err = cudaLaunchKernelEx(&cfg, cp_dot_kernel, x, beta0, y, n_rows);
    if (err != cudaSuccess) {
        // Fallback: plain serialized launch (still correct).
        cp_dot_kernel<<<grid, 256>>>(x, beta0, y, n_rows);
    }
}